// round 6
// baseline (speedup 1.0000x reference)
#include <cuda_runtime.h>

#define NB 4
#define NS 512
#define ND 256
#define NU 128
#define TI 8
#define NT (NS / TI)   // 64 i-tiles per batch

// scratch (allocation-free rule: __device__ globals)
__device__ float g_Q [NB * NS * NU];        // [row][u]                1 MB
__device__ float g_Vt[NB * NU * NS];        // [b][u][j]               1 MB
__device__ float g_S [NB * NT * NS * TI];   // [b][it][j][ti] scores   4 MB

__device__ __forceinline__ float fast_tanh(float x) {
    float r;
    asm("tanh.approx.f32 %0, %1;" : "=f"(r) : "f"(x));
    return r;
}

// ---------------------------------------------------------------------------
// Pass 1: Q = values @ Wq -> g_Q ;  V = values @ Wv -> g_Vt (transposed).
// grid 256 x 256 thr: block owns 8 rows, warp owns 1 row, lane owns u-quad.
// W staged in smem k-chunks of 32 -> inner loop is 3 LDS + 8 FFMA.
// ---------------------------------------------------------------------------
#define KC 32
__global__ __launch_bounds__(256) void proj_kernel(
    const float* __restrict__ values,
    const float* __restrict__ Wq,
    const float* __restrict__ Wv)
{
    __shared__ float4 sW[2][KC][NU / 4];   // 32 KB
    __shared__ float  vals[8][ND];         // 8 KB

    const int tid  = threadIdx.x;
    const int w    = tid >> 5;
    const int lane = tid & 31;
    const int r0   = blockIdx.x * 8;

    // stage 8 rows of values (512 float4, 2 per thread), coalesced
    {
        const float4* g4 = (const float4*)(values + (size_t)r0 * ND);
        float4* s4 = (float4*)&vals[0][0];
        s4[tid]       = g4[tid];
        s4[tid + 256] = g4[tid + 256];
    }

    float4 aq = {0,0,0,0}, av = {0,0,0,0};
    const float* vr = vals[w];

    for (int kc = 0; kc < ND; kc += KC) {
        __syncthreads();
        // stage W chunk: 2 mats x 32k x 32 quads = 2048 float4, 8 per thread
        {
            const float4* wq4 = (const float4*)(Wq + (size_t)kc * NU);
            const float4* wv4 = (const float4*)(Wv + (size_t)kc * NU);
#pragma unroll
            for (int i = 0; i < 4; i++) {
                const int idx = tid + i * 256;
                sW[0][idx >> 5][idx & 31] = wq4[idx];
                sW[1][idx >> 5][idx & 31] = wv4[idx];
            }
        }
        __syncthreads();

#pragma unroll 8
        for (int k = 0; k < KC; k++) {
            const float  x  = vr[kc + k];           // LDS broadcast (w uniform)
            const float4 wq = sW[0][k][lane];       // LDS.128 conflict-free
            const float4 wv = sW[1][k][lane];
            aq.x += x * wq.x;  aq.y += x * wq.y;  aq.z += x * wq.z;  aq.w += x * wq.w;
            av.x += x * wv.x;  av.y += x * wv.y;  av.z += x * wv.z;  av.w += x * wv.w;
        }
    }

    // write out: Q row-major (STG.128), Vt transposed scatter (4x STG.32)
    {
        const int row = r0 + w;
        ((float4*)(g_Q + (size_t)row * NU))[lane] = aq;

        const int b = row >> 9;
        const int s = row & (NS - 1);
        float* vt = g_Vt + ((size_t)b * NU + 4 * lane) * NS + s;
        vt[0 * NS] = av.x;
        vt[1 * NS] = av.y;
        vt[2 * NS] = av.z;
        vt[3 * NS] = av.w;
    }
}

// ---------------------------------------------------------------------------
// Pass 2: scores, uniform warp-tiles of 8i x 32j, causal-only, big-first.
// grid = (256, 4): x -> (it desc, j-quarter), y -> b. 128 threads (4 warps).
// ---------------------------------------------------------------------------
__global__ __launch_bounds__(128) void score_kernel(const float* __restrict__ Vw)
{
    __shared__ float qt[NU][TI];
    __shared__ float vw[NU];

    const int b  = blockIdx.y;
    const int x  = blockIdx.x;
    const int it = (NT - 1) - (x >> 2);     // big tiles first
    const int jq = x & 3;
    const int i0 = it * TI;
    const int jcount = i0 + TI;

    if (jq * 128 >= jcount) return;         // uniform across block

    const int tid  = threadIdx.x;
    const int w    = tid >> 5;
    const int lane = tid & 31;

    for (int e = tid; e < TI * NU; e += 128) {
        const int ti = e >> 7, u = e & 127;
        qt[u][ti] = g_Q[(b * NS + i0 + ti) * NU + u];
    }
    if (tid < NU) vw[tid] = Vw[tid];
    __syncthreads();

    const int jbase = jq * 128 + w * 32;
    if (jbase >= jcount) return;            // after the only barrier: safe
    const int j = jbase + lane;             // always < NS

    const float*  vp  = g_Vt + (size_t)b * (NU * NS) + j;
    const float4* qt4 = (const float4*)&qt[0][0];

    float a0 = 0.f, a1 = 0.f, a2 = 0.f, a3 = 0.f;
    float a4 = 0.f, a5 = 0.f, a6 = 0.f, a7 = 0.f;

#pragma unroll 4
    for (int u = 0; u < NU; u++) {
        const float v  = vp[u * NS];        // coalesced, L2-resident
        const float wu = vw[u];
        const float4 qa = qt4[u * 2];
        const float4 qb = qt4[u * 2 + 1];
        a0 += wu * fast_tanh(qa.x + v);
        a1 += wu * fast_tanh(qa.y + v);
        a2 += wu * fast_tanh(qa.z + v);
        a3 += wu * fast_tanh(qa.w + v);
        a4 += wu * fast_tanh(qb.x + v);
        a5 += wu * fast_tanh(qb.y + v);
        a6 += wu * fast_tanh(qb.z + v);
        a7 += wu * fast_tanh(qb.w + v);
    }

    if (j < jcount) {
        // causal mask -> exact 0 (excluded from softmax, nullified in context)
        float4 s0 = make_float4(j <= i0     ? a0 : 0.f,
                                j <= i0 + 1 ? a1 : 0.f,
                                j <= i0 + 2 ? a2 : 0.f,
                                j <= i0 + 3 ? a3 : 0.f);
        float4 s1 = make_float4(j <= i0 + 4 ? a4 : 0.f,
                                j <= i0 + 5 ? a5 : 0.f,
                                j <= i0 + 6 ? a6 : 0.f,
                                j <= i0 + 7 ? a7 : 0.f);
        float4* dst = (float4*)(g_S + ((size_t)(b * NT + it) * NS + j) * TI);
        dst[0] = s0;                         // 2x STG.128, 1KB/warp contiguous
        dst[1] = s1;
    }
}

// ---------------------------------------------------------------------------
// Pass 3: softmax + context. grid = (64, 4) x 256 thr: block owns one i-tile,
// warp w owns softmax row w, thread owns one d column for all 8 rows.
// ---------------------------------------------------------------------------
__global__ __launch_bounds__(256) void ctx_kernel(
    const float* __restrict__ values,
    float* __restrict__ out)
{
    __shared__ float4 at4[NS * 2];          // at[j][ti], 16 KB

    const int b  = blockIdx.y;
    const int it = (NT - 1) - blockIdx.x;   // big tiles first
    const int i0 = it * TI;
    const int jcount = i0 + TI;

    const int tid  = threadIdx.x;
    const int w    = tid >> 5;
    const int lane = tid & 31;

    const float4* src = (const float4*)(g_S + (size_t)(b * NT + it) * NS * TI);
    for (int idx = tid; idx < jcount * 2; idx += 256)
        at4[idx] = src[idx];
    __syncthreads();

    // softmax: warp w owns query row i0+w, over j in [0, i0+w]
    {
        float* at = (float*)at4;
        const int cnt = i0 + w + 1;

        float m = -1e30f;
        for (int jj = lane; jj < cnt; jj += 32)
            m = fmaxf(m, at[jj * TI + w]);
#pragma unroll
        for (int o = 16; o; o >>= 1)
            m = fmaxf(m, __shfl_xor_sync(0xffffffffu, m, o));

        float ssum = 0.f;
        for (int jj = lane; jj < cnt; jj += 32) {
            const float e = __expf(at[jj * TI + w] - m);
            at[jj * TI + w] = e;
            ssum += e;
        }
#pragma unroll
        for (int o = 16; o; o >>= 1)
            ssum += __shfl_xor_sync(0xffffffffu, ssum, o);

        const float inv = 1.f / ssum;
        for (int jj = lane; jj < cnt; jj += 32)
            at[jj * TI + w] *= inv;
    }
    __syncthreads();

    // context: thread owns one d column (D == 256 == blockDim)
    const int d = tid;
    float c0 = 0.f, c1 = 0.f, c2 = 0.f, c3 = 0.f;
    float c4 = 0.f, c5 = 0.f, c6 = 0.f, c7 = 0.f;

    const float* vb = values + (size_t)(b * NS) * ND + d;

#pragma unroll 8
    for (int j = 0; j < jcount; j++) {
        const float  v  = vb[(size_t)j * ND];   // coalesced 128B/warp
        const float4 p0 = at4[j * 2];           // LDS.128 broadcast
        const float4 p1 = at4[j * 2 + 1];
        c0 += p0.x * v;  c1 += p0.y * v;  c2 += p0.z * v;  c3 += p0.w * v;
        c4 += p1.x * v;  c5 += p1.y * v;  c6 += p1.z * v;  c7 += p1.w * v;
    }

    float cc[TI] = {c0, c1, c2, c3, c4, c5, c6, c7};
#pragma unroll
    for (int ti = 0; ti < TI; ti++)
        out[(size_t)(b * NS + i0 + ti) * ND + d] = cc[ti];
}

// ---------------------------------------------------------------------------
extern "C" void kernel_launch(void* const* d_in, const int* in_sizes, int n_in,
                              void* d_out, int out_size)
{
    const float* values = (const float*)d_in[0];
    const float* Wq     = (const float*)d_in[1];
    const float* Wv     = (const float*)d_in[2];
    const float* Vw     = (const float*)d_in[3];
    float* out = (float*)d_out;

    proj_kernel <<<(NB * NS) / 8, 256>>>(values, Wq, Wv);
    score_kernel<<<dim3(NT * 4, NB), 128>>>(Vw);
    ctx_kernel  <<<dim3(NT, NB), 256>>>(values, out);
}

// round 7
// speedup vs baseline: 1.6328x; 1.6328x over previous
#include <cuda_runtime.h>

#define NB 4
#define NS 512
#define ND 256
#define NU 128
#define TI 8
#define NT (NS / TI)   // 64 i-tiles per batch

// scratch (allocation-free rule: __device__ globals)
__device__ float g_Q [NB * NS * NU];        // [row][u]                1 MB
__device__ float g_Vt[NB * NU * NS];        // [b][u][j]               1 MB
__device__ float g_S [NB * NT * NS * TI];   // [b][it][j][ti] scores   4 MB

__device__ __forceinline__ float fast_tanh(float x) {
    float r;
    asm("tanh.approx.f32 %0, %1;" : "=f"(r) : "f"(x));
    return r;
}

// ---------------------------------------------------------------------------
// Pass 1: Q = values @ Wq -> g_Q ;  V = values @ Wv -> g_Vt (transposed).
// 128 blocks x 256 thr. Block: 16 rows. Warp owns 2 rows; lane owns u-quad.
// W double-buffered in smem k-chunks of 32: next chunk's LDG/STS issued
// before computing current chunk -> gmem latency overlapped with FFMA.
// ---------------------------------------------------------------------------
#define KC 32
__global__ __launch_bounds__(256) void proj_kernel(
    const float* __restrict__ values,
    const float* __restrict__ Wq,
    const float* __restrict__ Wv)
{
    __shared__ float4 sW[2][2][KC][NU / 4];  // [buf][mat][k][uq]  64 KB
    __shared__ float  vals[16][ND];          // 16 KB

    const int tid  = threadIdx.x;
    const int w    = tid >> 5;
    const int lane = tid & 31;
    const int r0   = blockIdx.x * 16;

    // stage 16 rows of values (1024 float4, 4 per thread), coalesced
    {
        const float4* g4 = (const float4*)(values + (size_t)r0 * ND);
        float4* s4 = (float4*)&vals[0][0];
#pragma unroll
        for (int i = 0; i < 4; i++)
            s4[tid + i * 256] = g4[tid + i * 256];
    }

    // stage W chunk 0 into buf 0 (2 mats x 32k x 32 quads = 2048 float4)
    {
        const float4* wq4 = (const float4*)Wq;
        const float4* wv4 = (const float4*)Wv;
#pragma unroll
        for (int i = 0; i < 4; i++) {
            const int idx = tid + i * 256;
            sW[0][0][idx >> 5][idx & 31] = wq4[idx];
            sW[0][1][idx >> 5][idx & 31] = wv4[idx];
        }
    }
    __syncthreads();

    float4 aq0 = {0,0,0,0}, aq1 = {0,0,0,0};
    float4 av0 = {0,0,0,0}, av1 = {0,0,0,0};

    const float* vr0 = vals[2 * w + 0];
    const float* vr1 = vals[2 * w + 1];

#pragma unroll 1
    for (int c = 0; c < ND / KC; c++) {
        const int buf = c & 1;

        // prefetch next chunk into the other buffer (overlaps with compute)
        if (c + 1 < ND / KC) {
            const float4* wq4 = (const float4*)(Wq + (size_t)(c + 1) * KC * NU);
            const float4* wv4 = (const float4*)(Wv + (size_t)(c + 1) * KC * NU);
#pragma unroll
            for (int i = 0; i < 4; i++) {
                const int idx = tid + i * 256;
                sW[buf ^ 1][0][idx >> 5][idx & 31] = wq4[idx];
                sW[buf ^ 1][1][idx >> 5][idx & 31] = wv4[idx];
            }
        }

        const int kc = c * KC;
#pragma unroll 8
        for (int k = 0; k < KC; k++) {
            const float  x0 = vr0[kc + k];            // LDS broadcast
            const float  x1 = vr1[kc + k];
            const float4 wq = sW[buf][0][k][lane];    // LDS.128 conflict-free
            const float4 wv = sW[buf][1][k][lane];
            aq0.x += x0 * wq.x;  aq0.y += x0 * wq.y;  aq0.z += x0 * wq.z;  aq0.w += x0 * wq.w;
            aq1.x += x1 * wq.x;  aq1.y += x1 * wq.y;  aq1.z += x1 * wq.z;  aq1.w += x1 * wq.w;
            av0.x += x0 * wv.x;  av0.y += x0 * wv.y;  av0.z += x0 * wv.z;  av0.w += x0 * wv.w;
            av1.x += x1 * wv.x;  av1.y += x1 * wv.y;  av1.z += x1 * wv.z;  av1.w += x1 * wv.w;
        }
        __syncthreads();   // next buffer fully staged before it is read
    }

    // write out: Q row-major (STG.128), Vt transposed scatter (4x STG.32/row)
#pragma unroll
    for (int rr = 0; rr < 2; rr++) {
        const int row = r0 + 2 * w + rr;
        const float4 aq = rr ? aq1 : aq0;
        const float4 av = rr ? av1 : av0;
        ((float4*)(g_Q + (size_t)row * NU))[lane] = aq;

        const int b = row >> 9;
        const int s = row & (NS - 1);
        float* vt = g_Vt + ((size_t)b * NU + 4 * lane) * NS + s;
        vt[0 * NS] = av.x;
        vt[1 * NS] = av.y;
        vt[2 * NS] = av.z;
        vt[3 * NS] = av.w;
    }
}

// ---------------------------------------------------------------------------
// Pass 2: scores, uniform warp-tiles of 8i x 32j, causal-only, big-first.
// grid = (256, 4): x -> (it desc, j-quarter), y -> b. 128 threads (4 warps).
// ---------------------------------------------------------------------------
__global__ __launch_bounds__(128) void score_kernel(const float* __restrict__ Vw)
{
    __shared__ float qt[NU][TI];
    __shared__ float vw[NU];

    const int b  = blockIdx.y;
    const int x  = blockIdx.x;
    const int it = (NT - 1) - (x >> 2);     // big tiles first
    const int jq = x & 3;
    const int i0 = it * TI;
    const int jcount = i0 + TI;

    if (jq * 128 >= jcount) return;         // uniform across block

    const int tid  = threadIdx.x;
    const int w    = tid >> 5;
    const int lane = tid & 31;

    for (int e = tid; e < TI * NU; e += 128) {
        const int ti = e >> 7, u = e & 127;
        qt[u][ti] = g_Q[(b * NS + i0 + ti) * NU + u];
    }
    if (tid < NU) vw[tid] = Vw[tid];
    __syncthreads();

    const int jbase = jq * 128 + w * 32;
    if (jbase >= jcount) return;            // after the only barrier: safe
    const int j = jbase + lane;             // always < NS

    const float*  vp  = g_Vt + (size_t)b * (NU * NS) + j;
    const float4* qt4 = (const float4*)&qt[0][0];

    float a0 = 0.f, a1 = 0.f, a2 = 0.f, a3 = 0.f;
    float a4 = 0.f, a5 = 0.f, a6 = 0.f, a7 = 0.f;

#pragma unroll 4
    for (int u = 0; u < NU; u++) {
        const float v  = vp[u * NS];        // coalesced, L2-resident
        const float wu = vw[u];
        const float4 qa = qt4[u * 2];
        const float4 qb = qt4[u * 2 + 1];
        a0 += wu * fast_tanh(qa.x + v);
        a1 += wu * fast_tanh(qa.y + v);
        a2 += wu * fast_tanh(qa.z + v);
        a3 += wu * fast_tanh(qa.w + v);
        a4 += wu * fast_tanh(qb.x + v);
        a5 += wu * fast_tanh(qb.y + v);
        a6 += wu * fast_tanh(qb.z + v);
        a7 += wu * fast_tanh(qb.w + v);
    }

    if (j < jcount) {
        // causal mask -> exact 0 (excluded from softmax, nullified in context)
        float4 s0 = make_float4(j <= i0     ? a0 : 0.f,
                                j <= i0 + 1 ? a1 : 0.f,
                                j <= i0 + 2 ? a2 : 0.f,
                                j <= i0 + 3 ? a3 : 0.f);
        float4 s1 = make_float4(j <= i0 + 4 ? a4 : 0.f,
                                j <= i0 + 5 ? a5 : 0.f,
                                j <= i0 + 6 ? a6 : 0.f,
                                j <= i0 + 7 ? a7 : 0.f);
        float4* dst = (float4*)(g_S + ((size_t)(b * NT + it) * NS + j) * TI);
        dst[0] = s0;                         // 2x STG.128, 1KB/warp contiguous
        dst[1] = s1;
    }
}

// ---------------------------------------------------------------------------
// Pass 3: softmax + context. grid = (128, 4): x -> (it desc, d-half), y -> b.
// 128 threads (4 warps). smem scores [j][8] loaded as straight float4 copy.
// ---------------------------------------------------------------------------
__global__ __launch_bounds__(128) void ctx_kernel(
    const float* __restrict__ values,
    float* __restrict__ out)
{
    __shared__ float4 at4[NS * 2];          // at[j][ti], 16 KB

    const int b  = blockIdx.y;
    const int x  = blockIdx.x;
    const int it = (NT - 1) - (x >> 1);     // big tiles first
    const int dh = x & 1;
    const int i0 = it * TI;
    const int jcount = i0 + TI;

    const int tid  = threadIdx.x;
    const int w    = tid >> 5;
    const int lane = tid & 31;

    const float4* src = (const float4*)(g_S + (size_t)(b * NT + it) * NS * TI);
    for (int idx = tid; idx < jcount * 2; idx += 128)
        at4[idx] = src[idx];
    __syncthreads();

    // softmax: 4 warps x 2 rows each (row r = w, w+4), over j in [0, i0+r]
    float* at = (float*)at4;
#pragma unroll
    for (int rr = 0; rr < 2; rr++) {
        const int r   = w + rr * 4;
        const int cnt = i0 + r + 1;

        float m = -1e30f;
        for (int jj = lane; jj < cnt; jj += 32)
            m = fmaxf(m, at[jj * TI + r]);
#pragma unroll
        for (int o = 16; o; o >>= 1)
            m = fmaxf(m, __shfl_xor_sync(0xffffffffu, m, o));

        float ssum = 0.f;
        for (int jj = lane; jj < cnt; jj += 32) {
            const float e = __expf(at[jj * TI + r] - m);
            at[jj * TI + r] = e;
            ssum += e;
        }
#pragma unroll
        for (int o = 16; o; o >>= 1)
            ssum += __shfl_xor_sync(0xffffffffu, ssum, o);

        const float inv = 1.f / ssum;
        for (int jj = lane; jj < cnt; jj += 32)
            at[jj * TI + r] *= inv;
    }
    __syncthreads();

    // context: thread owns one d column in its half; v reused across 8 rows.
    // unroll 8 -> 8 independent LDGs in flight (MLP 8).
    const int d = dh * 128 + tid;
    float c0 = 0.f, c1 = 0.f, c2 = 0.f, c3 = 0.f;
    float c4 = 0.f, c5 = 0.f, c6 = 0.f, c7 = 0.f;

    const float* vb = values + (size_t)(b * NS) * ND + d;

#pragma unroll 8
    for (int j = 0; j < jcount; j++) {
        const float  v  = vb[(size_t)j * ND];   // coalesced 128B/warp
        const float4 p0 = at4[j * 2];           // LDS.128 broadcast
        const float4 p1 = at4[j * 2 + 1];
        c0 += p0.x * v;  c1 += p0.y * v;  c2 += p0.z * v;  c3 += p0.w * v;
        c4 += p1.x * v;  c5 += p1.y * v;  c6 += p1.z * v;  c7 += p1.w * v;
    }

    float cc[TI] = {c0, c1, c2, c3, c4, c5, c6, c7};
#pragma unroll
    for (int ti = 0; ti < TI; ti++)
        out[(size_t)(b * NS + i0 + ti) * ND + d] = cc[ti];
}

// ---------------------------------------------------------------------------
extern "C" void kernel_launch(void* const* d_in, const int* in_sizes, int n_in,
                              void* d_out, int out_size)
{
    const float* values = (const float*)d_in[0];
    const float* Wq     = (const float*)d_in[1];
    const float* Wv     = (const float*)d_in[2];
    const float* Vw     = (const float*)d_in[3];
    float* out = (float*)d_out;

    proj_kernel <<<(NB * NS) / 16, 256>>>(values, Wq, Wv);
    score_kernel<<<dim3(NT * 4, NB), 128>>>(Vw);
    ctx_kernel  <<<dim3(NT * 2, NB), 128>>>(values, out);
}

// round 8
// speedup vs baseline: 1.8897x; 1.1573x over previous
#include <cuda_runtime.h>

#define NB 4
#define NS 512
#define ND 256
#define NU 128
#define TI 8
#define NT (NS / TI)   // 64 i-tiles per batch

// scratch (allocation-free rule: __device__ globals)
__device__ float g_Q [NB * NS * NU];        // [row][u]    1 MB
__device__ float g_Vt[NB * NU * NS];        // [b][u][j]   1 MB

__device__ __forceinline__ float fast_tanh(float x) {
    float r;
    asm("tanh.approx.f32 %0, %1;" : "=f"(r) : "f"(x));
    return r;
}

// ---------------------------------------------------------------------------
// Pass 1: Q = values @ Wq -> g_Q ;  V = values @ Wv -> g_Vt (transposed).
// 128 blocks x 256 thr. Block: 16 rows. Warp owns 2 rows; lane owns u-quad.
// W double-buffered in smem k-chunks of 32.
// ---------------------------------------------------------------------------
#define KC 32
__global__ __launch_bounds__(256) void proj_kernel(
    const float* __restrict__ values,
    const float* __restrict__ Wq,
    const float* __restrict__ Wv)
{
    __shared__ float4 sW[2][2][KC][NU / 4];  // [buf][mat][k][uq]  64 KB
    __shared__ float  vals[16][ND];          // 16 KB

    const int tid  = threadIdx.x;
    const int w    = tid >> 5;
    const int lane = tid & 31;
    const int r0   = blockIdx.x * 16;

    {
        const float4* g4 = (const float4*)(values + (size_t)r0 * ND);
        float4* s4 = (float4*)&vals[0][0];
#pragma unroll
        for (int i = 0; i < 4; i++)
            s4[tid + i * 256] = g4[tid + i * 256];
    }
    {
        const float4* wq4 = (const float4*)Wq;
        const float4* wv4 = (const float4*)Wv;
#pragma unroll
        for (int i = 0; i < 4; i++) {
            const int idx = tid + i * 256;
            sW[0][0][idx >> 5][idx & 31] = wq4[idx];
            sW[0][1][idx >> 5][idx & 31] = wv4[idx];
        }
    }
    __syncthreads();

    float4 aq0 = {0,0,0,0}, aq1 = {0,0,0,0};
    float4 av0 = {0,0,0,0}, av1 = {0,0,0,0};

    const float* vr0 = vals[2 * w + 0];
    const float* vr1 = vals[2 * w + 1];

#pragma unroll 1
    for (int c = 0; c < ND / KC; c++) {
        const int buf = c & 1;

        if (c + 1 < ND / KC) {
            const float4* wq4 = (const float4*)(Wq + (size_t)(c + 1) * KC * NU);
            const float4* wv4 = (const float4*)(Wv + (size_t)(c + 1) * KC * NU);
#pragma unroll
            for (int i = 0; i < 4; i++) {
                const int idx = tid + i * 256;
                sW[buf ^ 1][0][idx >> 5][idx & 31] = wq4[idx];
                sW[buf ^ 1][1][idx >> 5][idx & 31] = wv4[idx];
            }
        }

        const int kc = c * KC;
#pragma unroll 8
        for (int k = 0; k < KC; k++) {
            const float  x0 = vr0[kc + k];
            const float  x1 = vr1[kc + k];
            const float4 wq = sW[buf][0][k][lane];
            const float4 wv = sW[buf][1][k][lane];
            aq0.x += x0 * wq.x;  aq0.y += x0 * wq.y;  aq0.z += x0 * wq.z;  aq0.w += x0 * wq.w;
            aq1.x += x1 * wq.x;  aq1.y += x1 * wq.y;  aq1.z += x1 * wq.z;  aq1.w += x1 * wq.w;
            av0.x += x0 * wv.x;  av0.y += x0 * wv.y;  av0.z += x0 * wv.z;  av0.w += x0 * wv.w;
            av1.x += x1 * wv.x;  av1.y += x1 * wv.y;  av1.z += x1 * wv.z;  av1.w += x1 * wv.w;
        }
        __syncthreads();
    }

#pragma unroll
    for (int rr = 0; rr < 2; rr++) {
        const int row = r0 + 2 * w + rr;
        const float4 aq = rr ? aq1 : aq0;
        const float4 av = rr ? av1 : av0;
        ((float4*)(g_Q + (size_t)row * NU))[lane] = aq;

        const int b = row >> 9;
        const int s = row & (NS - 1);
        float* vt = g_Vt + ((size_t)b * NU + 4 * lane) * NS + s;
        vt[0 * NS] = av.x;
        vt[1 * NS] = av.y;
        vt[2 * NS] = av.z;
        vt[3 * NS] = av.w;
    }
}

// ---------------------------------------------------------------------------
// Pass 2 (fused): score(tanh) + causal softmax + context for one i-tile.
// grid = (64, 4) big-first, 256 threads (8 warps).
//   Phase A: warp w sweeps j-chunks {w, w+8, ...} of 32 j; scores -> smem at[]
//   softmax: warp w owns row w
//   Phase B: thread owns d column; 8 rows accumulated in registers
// ---------------------------------------------------------------------------
__global__ __launch_bounds__(256) void attn_kernel(
    const float* __restrict__ values,
    const float* __restrict__ Vw,
    float* __restrict__ out)
{
    __shared__ float4 at4[NS * 2];      // at[j][ti], 16 KB
    __shared__ float  qt[NU][TI];       // 4 KB
    __shared__ float  vw[NU];

    const int b  = blockIdx.y;
    const int it = (NT - 1) - blockIdx.x;   // big tiles first
    const int i0 = it * TI;
    const int jcount = i0 + TI;

    const int tid  = threadIdx.x;
    const int w    = tid >> 5;
    const int lane = tid & 31;

    // stage q transposed + Vw
    {
        const int ti = tid >> 7, u = tid & 127;      // 256 thr = 2 ti x 128 u
        qt[u][ti + 0] = g_Q[(b * NS + i0 + ti + 0) * NU + u];
        qt[u][ti + 2] = g_Q[(b * NS + i0 + ti + 2) * NU + u];
        qt[u][ti + 4] = g_Q[(b * NS + i0 + ti + 4) * NU + u];
        qt[u][ti + 6] = g_Q[(b * NS + i0 + ti + 6) * NU + u];
    }
    if (tid < NU) vw[tid] = Vw[tid];
    __syncthreads();

    // ---- Phase A: scores, warp-chunks of 32 j
    {
        const int nJ32 = (jcount + 31) >> 5;
        const float4* qt4 = (const float4*)&qt[0][0];

        for (int jt = w; jt < nJ32; jt += 8) {
            const int j = jt * 32 + lane;            // always < NS
            const float* vp = g_Vt + (size_t)b * (NU * NS) + j;

            float a0 = 0.f, a1 = 0.f, a2 = 0.f, a3 = 0.f;
            float a4 = 0.f, a5 = 0.f, a6 = 0.f, a7 = 0.f;

#pragma unroll 4
            for (int u = 0; u < NU; u++) {
                const float v  = vp[u * NS];         // coalesced, L2-resident
                const float wu = vw[u];
                const float4 qa = qt4[u * 2];
                const float4 qb = qt4[u * 2 + 1];
                a0 += wu * fast_tanh(qa.x + v);
                a1 += wu * fast_tanh(qa.y + v);
                a2 += wu * fast_tanh(qa.z + v);
                a3 += wu * fast_tanh(qa.w + v);
                a4 += wu * fast_tanh(qb.x + v);
                a5 += wu * fast_tanh(qb.y + v);
                a6 += wu * fast_tanh(qb.z + v);
                a7 += wu * fast_tanh(qb.w + v);
            }

            if (j < jcount) {
                // causal mask -> exact 0 (excluded from softmax & context)
                at4[j * 2]     = make_float4(j <= i0     ? a0 : 0.f,
                                             j <= i0 + 1 ? a1 : 0.f,
                                             j <= i0 + 2 ? a2 : 0.f,
                                             j <= i0 + 3 ? a3 : 0.f);
                at4[j * 2 + 1] = make_float4(j <= i0 + 4 ? a4 : 0.f,
                                             j <= i0 + 5 ? a5 : 0.f,
                                             j <= i0 + 6 ? a6 : 0.f,
                                             j <= i0 + 7 ? a7 : 0.f);
            }
        }
    }
    __syncthreads();

    // ---- softmax: warp w owns query row i0+w, over j in [0, i0+w]
    {
        float* at = (float*)at4;
        const int cnt = i0 + w + 1;

        float m = -1e30f;
        for (int jj = lane; jj < cnt; jj += 32)
            m = fmaxf(m, at[jj * TI + w]);
#pragma unroll
        for (int o = 16; o; o >>= 1)
            m = fmaxf(m, __shfl_xor_sync(0xffffffffu, m, o));

        float ssum = 0.f;
        for (int jj = lane; jj < cnt; jj += 32) {
            const float e = __expf(at[jj * TI + w] - m);
            at[jj * TI + w] = e;
            ssum += e;
        }
#pragma unroll
        for (int o = 16; o; o >>= 1)
            ssum += __shfl_xor_sync(0xffffffffu, ssum, o);

        const float inv = 1.f / ssum;
        for (int jj = lane; jj < cnt; jj += 32)
            at[jj * TI + w] *= inv;
    }
    __syncthreads();

    // ---- Phase B: context, thread owns d column (D == 256 == blockDim)
    const int d = tid;
    float c0 = 0.f, c1 = 0.f, c2 = 0.f, c3 = 0.f;
    float c4 = 0.f, c5 = 0.f, c6 = 0.f, c7 = 0.f;

    const float* vb = values + (size_t)(b * NS) * ND + d;

#pragma unroll 8
    for (int j = 0; j < jcount; j++) {
        const float  v  = vb[(size_t)j * ND];   // coalesced 128B/warp
        const float4 p0 = at4[j * 2];           // LDS.128 broadcast
        const float4 p1 = at4[j * 2 + 1];
        c0 += p0.x * v;  c1 += p0.y * v;  c2 += p0.z * v;  c3 += p0.w * v;
        c4 += p1.x * v;  c5 += p1.y * v;  c6 += p1.z * v;  c7 += p1.w * v;
    }

    float cc[TI] = {c0, c1, c2, c3, c4, c5, c6, c7};
#pragma unroll
    for (int ti = 0; ti < TI; ti++)
        out[(size_t)(b * NS + i0 + ti) * ND + d] = cc[ti];
}

// ---------------------------------------------------------------------------
extern "C" void kernel_launch(void* const* d_in, const int* in_sizes, int n_in,
                              void* d_out, int out_size)
{
    const float* values = (const float*)d_in[0];
    const float* Wq     = (const float*)d_in[1];
    const float* Wv     = (const float*)d_in[2];
    const float* Vw     = (const float*)d_in[3];
    float* out = (float*)d_out;

    proj_kernel<<<(NB * NS) / 16, 256>>>(values, Wq, Wv);
    attn_kernel<<<dim3(NT, NB), 256>>>(values, Vw, out);
}